// round 1
// baseline (speedup 1.0000x reference)
#include <cuda_runtime.h>
#include <math.h>

#define N    8192
#define FIN  128
#define FOUT 64
#define RI   16      // rows per block in main kernel
#define TJ   128     // j-chunk size

// Scratch (allocation-free rule: __device__ globals)
__device__ __align__(128) float g_Wh[N * FOUT];   // x @ W^T
__device__ __align__(128) float g_B1[N];          // exp(Wh2[j])
__device__ __align__(128) float g_B2[N];          // exp(0.2*Wh2[j])
__device__ __align__(128) float g_w1[N];          // Wh1[i]
__device__ __align__(128) float g_r[N];           // exp(-0.8*Wh1[i])
__device__ __align__(128) float g_Wh2[N];         // Wh2[j]

// ---------------------------------------------------------------------------
// Kernel 1: Wh = x @ W^T.  4 rows per block, W transposed into smem.
// ---------------------------------------------------------------------------
__global__ void k_wh(const float* __restrict__ x, const float* __restrict__ W) {
    __shared__ float Wt[FIN * FOUT];   // [c][k], conflict-free reads (k = lane)
    __shared__ float xs[4 * FIN];
    const int t = threadIdx.x;         // 256 threads
    const int row0 = blockIdx.x * 4;

    for (int idx = t; idx < FIN * FOUT; idx += 256) {
        int k = idx >> 7;       // W is [FOUT][FIN] row-major
        int c = idx & 127;
        Wt[c * FOUT + k] = W[idx];
    }
    for (int idx = t; idx < 4 * FIN; idx += 256)
        xs[idx] = x[(size_t)row0 * FIN + idx];
    __syncthreads();

    const int r = t >> 6;   // 0..3
    const int k = t & 63;   // 0..63
    float acc = 0.f;
#pragma unroll 16
    for (int c = 0; c < FIN; c++)
        acc = fmaf(xs[r * FIN + c], Wt[c * FOUT + k], acc);
    g_Wh[(size_t)(row0 + r) * FOUT + k] = acc;
}

// ---------------------------------------------------------------------------
// Kernel 2: per-row scalars  Wh1, Wh2 -> r, B1, B2.  One warp per row.
// ---------------------------------------------------------------------------
__global__ void k_rows(const float* __restrict__ a) {
    const int i = blockIdx.x * 8 + threadIdx.y;   // blockDim = (32, 8)
    const int lane = threadIdx.x;
    const float v0 = g_Wh[(size_t)i * FOUT + lane];
    const float v1 = g_Wh[(size_t)i * FOUT + 32 + lane];
    float s1 = v0 * a[lane]      + v1 * a[32 + lane];   // Wh . a1
    float s2 = v0 * a[64 + lane] + v1 * a[96 + lane];   // Wh . a2
#pragma unroll
    for (int o = 16; o; o >>= 1) {
        s1 += __shfl_xor_sync(0xffffffffu, s1, o);
        s2 += __shfl_xor_sync(0xffffffffu, s2, o);
    }
    if (lane == 0) {
        g_w1[i]  = s1;
        g_r[i]   = expf(-0.8f * s1);
        g_Wh2[i] = s2;
        g_B1[i]  = expf(s2);
        g_B2[i]  = expf(0.2f * s2);
    }
}

__device__ __forceinline__ float elu_f(float v) {
    return v > 0.f ? v : expm1f(v);
}

// ---------------------------------------------------------------------------
// Kernel 3: main fused masked-softmax-matmul.
// Block: 128 threads, RI=16 rows, j processed in TJ=128 chunks.
//  Phase A: 16 rows x 8 slots; each thread computes 16 masked weights q, STS.
//  Phase B: warp = 4 rows x 8 col-groups; thread owns cols [4cg,4cg+4) and
//           [32+4cg, 32+4cg+4)  (disjoint-bank LDS.128 pattern).
// ---------------------------------------------------------------------------
__global__ void __launch_bounds__(128, 4) k_main(const int* __restrict__ adj,
                                                 float* __restrict__ out) {
    __shared__ float Wh_s[TJ * FOUT];          // 32 KB
    __shared__ float q_s[RI][TJ + 4];          // padded pitch: conflict-free
    __shared__ float w1_s[RI], r_s[RI];
    __shared__ float dsum[RI][9];

    const int t = threadIdx.x;
    const int row0 = blockIdx.x * RI;

    if (t < RI) { w1_s[t] = g_w1[row0 + t]; r_s[t] = g_r[row0 + t]; }
    __syncthreads();

    // phase A mapping
    const int ruA = t >> 3;           // 0..15
    const int slA = t & 7;            // 0..7 (16 j's each)
    const float w1A = w1_s[ruA];
    const float rA  = r_s[ruA];
    const size_t adj_row = (size_t)(row0 + ruA) * N;

    // phase B mapping
    const int rowB = ((t >> 5) << 2) + ((t >> 3) & 3);  // 0..15
    const int cg   = t & 7;                              // 0..7

    float acc[8];
#pragma unroll
    for (int u = 0; u < 8; u++) acc[u] = 0.f;
    float dpart = 0.f;

    for (int jb = 0; jb < N; jb += TJ) {
        // stage Wh chunk: 8192 floats = 2048 float4, 128 threads x 16
        {
            const float4* src = (const float4*)(g_Wh + (size_t)jb * FOUT);
            float4* dst = (float4*)Wh_s;
#pragma unroll
            for (int u = 0; u < 16; u++)
                dst[t + u * 128] = src[t + u * 128];
        }

        // phase A: masked weights q for this block's 16 rows x 128 j
        const int j0 = jb + slA * 16;
#pragma unroll
        for (int u = 0; u < 4; u++) {
            const int jj = slA * 16 + u * 4;
            int4 m = __ldcs((const int4*)(adj + adj_row + (size_t)jb + jj));
            float4 b1 = *(const float4*)(g_B1  + j0 + u * 4);
            float4 b2 = *(const float4*)(g_B2  + j0 + u * 4);
            float4 h2 = *(const float4*)(g_Wh2 + j0 + u * 4);
            float q0 = (w1A + h2.x > 0.f) ? b1.x : rA * b2.x; if (!m.x) q0 = 0.f;
            float q1 = (w1A + h2.y > 0.f) ? b1.y : rA * b2.y; if (!m.y) q1 = 0.f;
            float q2 = (w1A + h2.z > 0.f) ? b1.z : rA * b2.z; if (!m.z) q2 = 0.f;
            float q3 = (w1A + h2.w > 0.f) ? b1.w : rA * b2.w; if (!m.w) q3 = 0.f;
            dpart += q0 + q1 + q2 + q3;
            q_s[ruA][jj + 0] = q0;
            q_s[ruA][jj + 1] = q1;
            q_s[ruA][jj + 2] = q2;
            q_s[ruA][jj + 3] = q3;
        }
        __syncthreads();

        // phase B: acc += q * Wh[j]
        const float4* whp = (const float4*)Wh_s;
#pragma unroll 4
        for (int jj = 0; jj < TJ; jj++) {
            const float q = q_s[rowB][jj];
            const float4 wa = whp[jj * 16 + cg];
            const float4 wb = whp[jj * 16 + 8 + cg];
            acc[0] = fmaf(q, wa.x, acc[0]);
            acc[1] = fmaf(q, wa.y, acc[1]);
            acc[2] = fmaf(q, wa.z, acc[2]);
            acc[3] = fmaf(q, wa.w, acc[3]);
            acc[4] = fmaf(q, wb.x, acc[4]);
            acc[5] = fmaf(q, wb.y, acc[5]);
            acc[6] = fmaf(q, wb.z, acc[6]);
            acc[7] = fmaf(q, wb.w, acc[7]);
        }
        __syncthreads();
    }

    // denominator reduction (phase-A layout -> per-row)
    dsum[ruA][slA] = dpart;
    __syncthreads();
    if (t < RI) {
        float d = 0.f;
#pragma unroll
        for (int s = 0; s < 8; s++) d += dsum[t][s];
        dsum[t][8] = d;
    }
    __syncthreads();

    const float inv = 1.0f / dsum[rowB][8];
    float* op = out + (size_t)(row0 + rowB) * FOUT + cg * 4;
    float4 o0, o1;
    o0.x = elu_f(acc[0] * inv);
    o0.y = elu_f(acc[1] * inv);
    o0.z = elu_f(acc[2] * inv);
    o0.w = elu_f(acc[3] * inv);
    o1.x = elu_f(acc[4] * inv);
    o1.y = elu_f(acc[5] * inv);
    o1.z = elu_f(acc[6] * inv);
    o1.w = elu_f(acc[7] * inv);
    *(float4*)op        = o0;
    *(float4*)(op + 32) = o1;
}

// ---------------------------------------------------------------------------
extern "C" void kernel_launch(void* const* d_in, const int* in_sizes, int n_in,
                              void* d_out, int out_size) {
    const float* x   = (const float*)d_in[0];
    const int*   adj = (const int*)d_in[1];
    const float* W   = (const float*)d_in[2];
    const float* a   = (const float*)d_in[3];
    float* out = (float*)d_out;

    k_wh<<<N / 4, 256>>>(x, W);
    k_rows<<<N / 8, dim3(32, 8)>>>(a);
    k_main<<<N / RI, 128>>>(adj, out);
}